// round 3
// baseline (speedup 1.0000x reference)
#include <cuda_runtime.h>
#include <math.h>

#define B_TOTAL 16384
#define F_DIM   512
#define P_DIM   128
#define C_DIM   10

#define BM  128
#define BK  16
#define TPB 256

// ---------------- device-global precomputed small tensors ----------------
__device__ float g_wsq[P_DIM];
__device__ float g_gamma[P_DIM];
__device__ float g_alpha[P_DIM];
__device__ float g_u[C_DIM * P_DIM];   // [c][p]

// ---------------- packed f32x2 helpers (Blackwell 2xFP32 path) ----------------
__device__ __forceinline__ unsigned long long pack2dup(float x) {
    unsigned long long r;
    asm("mov.b64 %0, {%1, %1};" : "=l"(r) : "f"(x));
    return r;
}
__device__ __forceinline__ void ffma2(unsigned long long& d,
                                      unsigned long long a,
                                      unsigned long long b) {
    asm("fma.rn.f32x2 %0, %1, %2, %0;" : "+l"(d) : "l"(a), "l"(b));
}
__device__ __forceinline__ float2 unpack2(unsigned long long v) {
    float2 f;
    asm("mov.b64 {%0, %1}, %2;" : "=f"(f.x), "=f"(f.y) : "l"(v));
    return f;
}

// ---------------- precompute kernel ----------------
__global__ void ds_precomp(const float* __restrict__ w,
                           const float* __restrict__ eta,
                           const float* __restrict__ xi,
                           const float* __restrict__ beta) {
    int p = threadIdx.x;
    if (p >= P_DIM) return;
    // ||w_p||^2
    float s = 0.f;
    const float4* wr = (const float4*)(w + (size_t)p * F_DIM);
#pragma unroll 8
    for (int i = 0; i < F_DIM / 4; ++i) {
        float4 v = wr[i];
        s = fmaf(v.x, v.x, s);
        s = fmaf(v.y, v.y, s);
        s = fmaf(v.z, v.z, s);
        s = fmaf(v.w, v.w, s);
    }
    g_wsq[p] = s;
    float e = eta[p];
    g_gamma[p] = e * e;
    g_alpha[p] = 1.f / (1.f + expf(-xi[p]));
    float b2[C_DIM];
    float bs = 0.f;
#pragma unroll
    for (int c = 0; c < C_DIM; ++c) {
        float b = beta[c * P_DIM + p];
        b2[c] = b * b;
        bs += b2[c];
    }
    float inv = 1.f / bs;
#pragma unroll
    for (int c = 0; c < C_DIM; ++c) g_u[c * P_DIM + p] = b2[c] * inv;
}

// ---------------- main fused kernel ----------------
// smem layout (floats):
//   region A (union):
//     GEMM phase: xs [16][132] at 0, ws [16][132] at 2112
//     post-GEMM:  si [128 p][128 b] at 0   (16384 floats)
//   us  [10][128] at 16384
//   xns [128]     at 17664
#define SM_WS  2112
#define SM_US  16384
#define SM_XNS 17664
#define SM_FLOATS 17792   // 71168 bytes

__global__ void __launch_bounds__(TPB, 1)
ds_main(const float* __restrict__ x,
        const float* __restrict__ w,
        float* __restrict__ out) {
    extern __shared__ float sm[];
    float* xs  = sm;
    float* ws  = sm + SM_WS;
    float* si  = sm;            // reused after GEMM
    float* us  = sm + SM_US;
    float* xns = sm + SM_XNS;

    const int tid  = threadIdx.x;
    const int row0 = blockIdx.x * BM;
    const int tx   = tid & 15;   // col group
    const int ty   = tid >> 4;   // row group

    // stage u into smem
    for (int i = tid; i < C_DIM * P_DIM; i += TPB) us[i] = g_u[i];

    // accumulators: rows {ty*4+i, 64+ty*4+i}, col pairs from {tx*4.., 64+tx*4..}
    unsigned long long acc[8][4];
#pragma unroll
    for (int i = 0; i < 8; ++i)
#pragma unroll
        for (int j = 0; j < 4; ++j) acc[i][j] = 0ull;

    float xn = 0.f;   // per-row ||x||^2 (threads 0..127 own row tid)

    const float* xblk = x + (size_t)row0 * F_DIM;

    for (int kt = 0; kt < F_DIM / BK; ++kt) {
        // ---- load k-tile (transposed into smem) ----
#pragma unroll
        for (int v = 0; v < 2; ++v) {
            int idx = tid + v * 256;      // 0..511
            int r   = idx >> 2;           // 0..127
            int kq  = idx & 3;            // 0..3
            float4 xv = *(const float4*)(xblk + (size_t)r * F_DIM + kt * BK + kq * 4);
            xs[(kq * 4 + 0) * 132 + r] = xv.x;
            xs[(kq * 4 + 1) * 132 + r] = xv.y;
            xs[(kq * 4 + 2) * 132 + r] = xv.z;
            xs[(kq * 4 + 3) * 132 + r] = xv.w;
            float4 wv = *(const float4*)(w + (size_t)r * F_DIM + kt * BK + kq * 4);
            ws[(kq * 4 + 0) * 132 + r] = wv.x;
            ws[(kq * 4 + 1) * 132 + r] = wv.y;
            ws[(kq * 4 + 2) * 132 + r] = wv.z;
            ws[(kq * 4 + 3) * 132 + r] = wv.w;
        }
        __syncthreads();

        // fold ||x||^2 accumulation into the resident tile
        if (tid < BM) {
#pragma unroll
            for (int kk = 0; kk < BK; ++kk) {
                float v = xs[kk * 132 + tid];
                xn = fmaf(v, v, xn);
            }
        }

        // ---- FMA core ----
#pragma unroll
        for (int kk = 0; kk < BK; ++kk) {
            float4 xa = *(const float4*)(xs + kk * 132 + ty * 4);
            float4 xb = *(const float4*)(xs + kk * 132 + 64 + ty * 4);
            ulonglong2 wa = *(const ulonglong2*)(ws + kk * 132 + tx * 4);
            ulonglong2 wb = *(const ulonglong2*)(ws + kk * 132 + 64 + tx * 4);
            unsigned long long xd[8];
            xd[0] = pack2dup(xa.x); xd[1] = pack2dup(xa.y);
            xd[2] = pack2dup(xa.z); xd[3] = pack2dup(xa.w);
            xd[4] = pack2dup(xb.x); xd[5] = pack2dup(xb.y);
            xd[6] = pack2dup(xb.z); xd[7] = pack2dup(xb.w);
#pragma unroll
            for (int i = 0; i < 8; ++i) {
                ffma2(acc[i][0], xd[i], wa.x);
                ffma2(acc[i][1], xd[i], wa.y);
                ffma2(acc[i][2], xd[i], wb.x);
                ffma2(acc[i][3], xd[i], wb.y);
            }
        }
        __syncthreads();
    }

    if (tid < BM) xns[tid] = xn;
    __syncthreads();

    // ---- epilogue: d -> si, stored [p][b] for the scan ----
    {
        float wsqv[8], gamv[8], alpv[8];
#pragma unroll
        for (int jh = 0; jh < 2; ++jh)
#pragma unroll
            for (int j = 0; j < 4; ++j) {
                int c = jh * 64 + tx * 4 + j;
                wsqv[jh * 4 + j] = g_wsq[c];
                gamv[jh * 4 + j] = g_gamma[c];
                alpv[jh * 4 + j] = g_alpha[c];
            }
#pragma unroll
        for (int ih = 0; ih < 2; ++ih)
#pragma unroll
            for (int i = 0; i < 4; ++i) {
                int r = ih * 64 + ty * 4 + i;
                float xnr = xns[r];
#pragma unroll
                for (int jh = 0; jh < 2; ++jh)
#pragma unroll
                    for (int jp = 0; jp < 2; ++jp) {
                        float2 a = unpack2(acc[ih * 4 + i][jh * 2 + jp]);
                        int j0 = jh * 4 + jp * 2;
                        int c0 = jh * 64 + tx * 4 + jp * 2;
                        float d0 = xnr + wsqv[j0]     - 2.f * a.x;
                        float d1 = xnr + wsqv[j0 + 1] - 2.f * a.y;
                        float e0 = alpv[j0]     * expf(-gamv[j0]     * d0);
                        float e1 = alpv[j0 + 1] * expf(-gamv[j0 + 1] * d1);
                        si[c0 * 128 + r]       = e0;
                        si[(c0 + 1) * 128 + r] = e1;
                    }
            }
    }
    __syncthreads();

    // ---- Dempster scan: one thread per batch row ----
    if (tid < BM) {
        const int r = tid;
        float mx = 0.f;
        for (int p = 0; p < P_DIM; ++p) mx = fmaxf(mx, si[p * 128 + r]);
        const float sinv = 1.f / (mx + 1e-4f);

        // init with plate p=0
        float s = si[r] * sinv;
        float m[C_DIM];
#pragma unroll
        for (int k = 0; k < C_DIM; ++k) m[k] = us[k * P_DIM + 0] * s;
        float o = 1.f - s;

        for (int p = 1; p < P_DIM; ++p) {
            s = si[p * 128 + r] * sinv;
            float om = 1.f - s;
            float os = o * s;
#pragma unroll
            for (int k = 0; k < C_DIM; ++k) {
                float u = us[k * P_DIM + p];
                float t = fmaf(s, u, om);        // 1 - s + s*u
                m[k] = fmaf(m[k], t, os * u);
            }
            o = 3.f * o * om;                    // c_omega = 3*o1*o2
            if ((p & 7) == 7) {                  // scale-invariant renorm
                float ssum = o;
#pragma unroll
                for (int k = 0; k < C_DIM; ++k) ssum += m[k];
                float rinv = 1.f / ssum;
#pragma unroll
                for (int k = 0; k < C_DIM; ++k) m[k] *= rinv;
                o *= rinv;
            }
        }
        float ssum = o;
#pragma unroll
        for (int k = 0; k < C_DIM; ++k) ssum += m[k];
        float rinv = 1.f / ssum;
        float* op = out + (size_t)(row0 + r) * (C_DIM + 1);
#pragma unroll
        for (int k = 0; k < C_DIM; ++k) op[k] = m[k] * rinv;
        op[C_DIM] = o * rinv;
    }
}

// ---------------- launch ----------------
extern "C" void kernel_launch(void* const* d_in, const int* in_sizes, int n_in,
                              void* d_out, int out_size) {
    const float* x    = (const float*)d_in[0];
    const float* w    = (const float*)d_in[1];
    const float* eta  = (const float*)d_in[2];
    const float* xi   = (const float*)d_in[3];
    const float* beta = (const float*)d_in[4];
    float* out = (float*)d_out;

    ds_precomp<<<1, P_DIM>>>(w, eta, xi, beta);

    cudaFuncSetAttribute(ds_main, cudaFuncAttributeMaxDynamicSharedMemorySize,
                         SM_FLOATS * (int)sizeof(float));
    ds_main<<<B_TOTAL / BM, TPB, SM_FLOATS * (int)sizeof(float)>>>(x, w, out);
}